// round 1
// baseline (speedup 1.0000x reference)
#include <cuda_runtime.h>
#include <cstdint>

#define HIDDEN 1024
#define NHEADS 16
#define HD 64
#define RP 256
#define BATCH 4
#define SEQ 4096
#define NTOK (BATCH * SEQ)      /* 16384 */
#define QKVW (3 * HIDDEN)       /* 3072  */
#define NBH (BATCH * NHEADS)    /* 64    */
#define SCALE 0.125f            /* 64^-0.5 */
#define KEPS 1e-3f

// ---------------- scratch ----------------
__device__ float g_qkv[(size_t)NTOK * QKVW];       // 192 MB
__device__ float g_ctx[(size_t)NBH * RP * HD];     // 4 MB
__device__ float g_ksum[(size_t)NBH * RP];         // 64 KB

// ============================================================
// Kernel A: QKV GEMM  C[16384,3072] = X[16384,1024] @ W[1024,3072] + bias
// 128x128 tile, BK=8, 256 threads, 8x8 per thread, double-buffered smem.
// ============================================================
__global__ __launch_bounds__(256, 2) void qkv_gemm(
    const float* __restrict__ A, const float* __restrict__ B,
    const float* __restrict__ bias)
{
    __shared__ float As[2][8][128];
    __shared__ float Bs[2][8][128];

    const int tid  = threadIdx.x;
    const int row0 = blockIdx.y * 128;
    const int col0 = blockIdx.x * 128;
    const int tm   = (tid >> 4) << 3;    // 0..120
    const int tn   = (tid & 15) << 3;

    const int a_row = tid >> 1;          // 0..127
    const int a_col = (tid & 1) << 2;    // 0 or 4
    const int b_row = tid >> 5;          // 0..7
    const int b_col = (tid & 31) << 2;   // 0..124

    const float* Aptr = A + (size_t)(row0 + a_row) * HIDDEN + a_col;
    const float* Bptr = B + (size_t)b_row * QKVW + col0 + b_col;

    float acc[8][8];
#pragma unroll
    for (int i = 0; i < 8; ++i)
#pragma unroll
        for (int j = 0; j < 8; ++j) acc[i][j] = 0.f;

    // preload tile 0
    {
        float4 av = *(const float4*)Aptr;
        As[0][a_col + 0][a_row] = av.x;
        As[0][a_col + 1][a_row] = av.y;
        As[0][a_col + 2][a_row] = av.z;
        As[0][a_col + 3][a_row] = av.w;
        *(float4*)&Bs[0][b_row][b_col] = *(const float4*)Bptr;
    }
    __syncthreads();

    const int KT = HIDDEN / 8;
    int buf = 0;
    for (int kt = 0; kt < KT; ++kt) {
        float4 av, bv;
        const bool more = (kt + 1 < KT);
        if (more) {
            av = *(const float4*)(Aptr + (kt + 1) * 8);
            bv = *(const float4*)(Bptr + (size_t)(kt + 1) * 8 * QKVW);
        }
#pragma unroll
        for (int kk = 0; kk < 8; ++kk) {
            float af[8], bf[8];
            *(float4*)&af[0] = *(const float4*)&As[buf][kk][tm];
            *(float4*)&af[4] = *(const float4*)&As[buf][kk][tm + 4];
            *(float4*)&bf[0] = *(const float4*)&Bs[buf][kk][tn];
            *(float4*)&bf[4] = *(const float4*)&Bs[buf][kk][tn + 4];
#pragma unroll
            for (int i = 0; i < 8; ++i)
#pragma unroll
                for (int j = 0; j < 8; ++j)
                    acc[i][j] = fmaf(af[i], bf[j], acc[i][j]);
        }
        if (more) {
            const int nb = buf ^ 1;
            As[nb][a_col + 0][a_row] = av.x;
            As[nb][a_col + 1][a_row] = av.y;
            As[nb][a_col + 2][a_row] = av.z;
            As[nb][a_col + 3][a_row] = av.w;
            *(float4*)&Bs[nb][b_row][b_col] = bv;
            __syncthreads();
            buf = nb;
        }
    }

    // epilogue: add bias, store
    float bs0[4], bs1[4];
    *(float4*)bs0 = *(const float4*)&bias[col0 + tn];
    *(float4*)bs1 = *(const float4*)&bias[col0 + tn + 4];
#pragma unroll
    for (int i = 0; i < 8; ++i) {
        float4 o0, o1;
        o0.x = acc[i][0] + bs0[0]; o0.y = acc[i][1] + bs0[1];
        o0.z = acc[i][2] + bs0[2]; o0.w = acc[i][3] + bs0[3];
        o1.x = acc[i][4] + bs1[0]; o1.y = acc[i][5] + bs1[1];
        o1.z = acc[i][6] + bs1[2]; o1.w = acc[i][7] + bs1[3];
        float* cp = g_qkv + (size_t)(row0 + tm + i) * QKVW + col0 + tn;
        *(float4*)cp       = o0;
        *(float4*)(cp + 4) = o1;
    }
}

// ============================================================
// Zero kernel: clears context + ksum accumulators
// ============================================================
__global__ void zero_acc()
{
    const int i = blockIdx.x * blockDim.x + threadIdx.x;
    if (i < NBH * RP * HD) g_ctx[i] = 0.f;
    if (i < NBH * RP)      g_ksum[i] = 0.f;
}

// ============================================================
// Kernel B: per (chunk, bh): k' features + context/ksum accumulation
// grid (8, 64), 256 threads. Chunk = 512 rows, processed in 8 subtiles of 64.
// smem: projT[64][256], kbuf[64][64], vbuf[64][64], kp[64][256] = 160 KB
// ============================================================
#define SMEM_B_FLOATS (64 * 256 + 64 * 64 + 64 * 64 + 64 * 256)

__global__ __launch_bounds__(256) void ctx_kernel(const float* __restrict__ proj)
{
    extern __shared__ float sm[];
    float* projT = sm;                    // [kk][m]
    float* kbuf  = projT + 64 * 256;      // [r][kk]
    float* vbuf  = kbuf + 64 * 64;        // [r][d]
    float* kp    = vbuf + 64 * 64;        // [r][m]

    const int tid   = threadIdx.x;
    const int lane  = tid & 31;
    const int w     = tid >> 5;
    const int chunk = blockIdx.x;         // 0..7
    const int bh    = blockIdx.y;         // 0..63
    const int b     = bh >> 4, h = bh & 15;

    // projT[kk][m] = proj[m*64+kk]
    for (int idx = tid; idx < 64 * 256; idx += 256) {
        const int m = idx & 255, kk = idx >> 8;
        projT[kk * 256 + m] = proj[m * 64 + kk];
    }

    // ctx-phase thread mapping
    const int mg = tid >> 3;    // m block: mg*8 .. mg*8+7
    const int dg = tid & 7;     // d block: dg*8 .. dg*8+7
    float cacc[8][8];
#pragma unroll
    for (int i = 0; i < 8; ++i)
#pragma unroll
        for (int j = 0; j < 8; ++j) cacc[i][j] = 0.f;
    float ks_acc[8];
#pragma unroll
    for (int i = 0; i < 8; ++i) ks_acc[i] = 0.f;

    const float* qkvb = g_qkv + (size_t)b * SEQ * QKVW;
    const int kcol = HIDDEN + h * HD;
    const int vcol = 2 * HIDDEN + h * HD;
    const int r_ld = tid >> 2;            // 0..63
    const int c_ld = (tid & 3) << 4;      // 0,16,32,48

    __syncthreads();   // projT ready

    for (int st = 0; st < 8; ++st) {
        const int n0 = chunk * 512 + st * 64;
        // load k (scaled) and v
#pragma unroll
        for (int q = 0; q < 4; ++q) {
            const size_t rbase = (size_t)(n0 + r_ld) * QKVW;
            float4 kv = *(const float4*)(qkvb + rbase + kcol + c_ld + q * 4);
            kv.x *= SCALE; kv.y *= SCALE; kv.z *= SCALE; kv.w *= SCALE;
            *(float4*)&kbuf[r_ld * 64 + c_ld + q * 4] = kv;
            *(float4*)&vbuf[r_ld * 64 + c_ld + q * 4] =
                *(const float4*)(qkvb + rbase + vcol + c_ld + q * 4);
        }
        __syncthreads();

        // feature phase: warp w handles rows w*8 .. w*8+7, lane owns m = lane+32j
        {
            float facc[8][8];
#pragma unroll
            for (int i = 0; i < 8; ++i)
#pragma unroll
                for (int j = 0; j < 8; ++j) facc[i][j] = 0.f;
#pragma unroll 4
            for (int kk = 0; kk < 64; ++kk) {
                float pj[8];
#pragma unroll
                for (int j = 0; j < 8; ++j) pj[j] = projT[kk * 256 + lane + 32 * j];
#pragma unroll
                for (int i = 0; i < 8; ++i) {
                    const float kv = kbuf[(w * 8 + i) * 64 + kk];
#pragma unroll
                    for (int j = 0; j < 8; ++j)
                        facc[i][j] = fmaf(kv, pj[j], facc[i][j]);
                }
            }
#pragma unroll
            for (int i = 0; i < 8; ++i)
#pragma unroll
                for (int j = 0; j < 8; ++j)
                    kp[(w * 8 + i) * 256 + lane + 32 * j] =
                        fmaxf(facc[i][j], 0.f) + KEPS;
        }
        __syncthreads();

        // context accumulation: ctx[m][d] += sum_r kp[r][m] * v[r][d]
#pragma unroll 4
        for (int r = 0; r < 64; ++r) {
            float kpv[8], vv[8];
            *(float4*)&kpv[0] = *(const float4*)&kp[r * 256 + mg * 8];
            *(float4*)&kpv[4] = *(const float4*)&kp[r * 256 + mg * 8 + 4];
            *(float4*)&vv[0]  = *(const float4*)&vbuf[r * 64 + dg * 8];
            *(float4*)&vv[4]  = *(const float4*)&vbuf[r * 64 + dg * 8 + 4];
#pragma unroll
            for (int i = 0; i < 8; ++i)
#pragma unroll
                for (int j = 0; j < 8; ++j)
                    cacc[i][j] = fmaf(kpv[i], vv[j], cacc[i][j]);
            if (dg == 0) {
#pragma unroll
                for (int i = 0; i < 8; ++i) ks_acc[i] += kpv[i];
            }
        }
        __syncthreads();
    }

    float* ctx_out = g_ctx + (size_t)bh * RP * HD;
#pragma unroll
    for (int i = 0; i < 8; ++i)
#pragma unroll
        for (int j = 0; j < 8; ++j)
            atomicAdd(&ctx_out[(mg * 8 + i) * HD + dg * 8 + j], cacc[i][j]);
    if (dg == 0) {
#pragma unroll
        for (int i = 0; i < 8; ++i)
            atomicAdd(&g_ksum[bh * RP + mg * 8 + i], ks_acc[i]);
    }
}

// ============================================================
// Kernel C: per (tile, bh): q' features + denom + out = (q' @ ctx) * dinv
// grid (64, 64), 256 threads. Tile = 64 rows.
// smem: projT 64K, ctxs 64K, qp 64K, qbuf 16K, ksums 1K, dinv 256B ≈ 210 KB
// ============================================================
#define SMEM_C_FLOATS (64 * 256 + 256 * 64 + 64 * 256 + 64 * 64 + 256 + 64)

__global__ __launch_bounds__(256) void out_kernel(const float* __restrict__ proj,
                                                  float* __restrict__ out)
{
    extern __shared__ float sm[];
    float* projT = sm;                     // [kk][m]
    float* ctxs  = projT + 64 * 256;       // [m][d]
    float* qp    = ctxs + 256 * 64;        // [r][m]
    float* qbuf  = qp + 64 * 256;          // [r][kk]
    float* ksums = qbuf + 64 * 64;         // [m]
    float* dinv  = ksums + 256;            // [r]

    const int tid  = threadIdx.x;
    const int lane = tid & 31;
    const int w    = tid >> 5;
    const int tile = blockIdx.x;           // 0..63
    const int bh   = blockIdx.y;
    const int b    = bh >> 4, h = bh & 15;
    const int n0   = tile * 64;

    for (int idx = tid; idx < 64 * 256; idx += 256) {
        const int m = idx & 255, kk = idx >> 8;
        projT[kk * 256 + m] = proj[m * 64 + kk];
    }
    for (int idx = tid; idx < 256 * 64; idx += 256)
        ctxs[idx] = g_ctx[(size_t)bh * RP * HD + idx];
    if (tid < 256) ksums[tid] = g_ksum[bh * RP + tid];

    // load q tile (scaled)
    {
        const float* qkvb = g_qkv + (size_t)b * SEQ * QKVW;
        const int qcol = h * HD;
        const int r_ld = tid >> 2;
        const int c_ld = (tid & 3) << 4;
#pragma unroll
        for (int q = 0; q < 4; ++q) {
            float4 qv = *(const float4*)(qkvb + (size_t)(n0 + r_ld) * QKVW + qcol + c_ld + q * 4);
            qv.x *= SCALE; qv.y *= SCALE; qv.z *= SCALE; qv.w *= SCALE;
            *(float4*)&qbuf[r_ld * 64 + c_ld + q * 4] = qv;
        }
    }
    __syncthreads();

    // feature phase + denominator
    {
        float facc[8][8];
#pragma unroll
        for (int i = 0; i < 8; ++i)
#pragma unroll
            for (int j = 0; j < 8; ++j) facc[i][j] = 0.f;
#pragma unroll 4
        for (int kk = 0; kk < 64; ++kk) {
            float pj[8];
#pragma unroll
            for (int j = 0; j < 8; ++j) pj[j] = projT[kk * 256 + lane + 32 * j];
#pragma unroll
            for (int i = 0; i < 8; ++i) {
                const float qv = qbuf[(w * 8 + i) * 64 + kk];
#pragma unroll
                for (int j = 0; j < 8; ++j)
                    facc[i][j] = fmaf(qv, pj[j], facc[i][j]);
            }
        }
#pragma unroll
        for (int i = 0; i < 8; ++i) {
            float dsum = 0.f;
#pragma unroll
            for (int j = 0; j < 8; ++j) {
                const float v = fmaxf(facc[i][j], 0.f) + KEPS;
                qp[(w * 8 + i) * 256 + lane + 32 * j] = v;
                dsum = fmaf(v, ksums[lane + 32 * j], dsum);
            }
#pragma unroll
            for (int off = 16; off > 0; off >>= 1)
                dsum += __shfl_xor_sync(0xFFFFFFFFu, dsum, off);
            if (lane == 0) dinv[w * 8 + i] = 1.0f / dsum;
        }
    }
    __syncthreads();

    // out phase: thread (rg,dg): rows rg*2,rg*2+1 ; d = dg*8..dg*8+7
    const int rg = tid >> 3;   // 0..31
    const int dg = tid & 7;
    float oacc[2][8];
#pragma unroll
    for (int i = 0; i < 2; ++i)
#pragma unroll
        for (int j = 0; j < 8; ++j) oacc[i][j] = 0.f;

#pragma unroll 4
    for (int m = 0; m < 256; ++m) {
        float c8[8];
        *(float4*)&c8[0] = *(const float4*)&ctxs[m * 64 + dg * 8];
        *(float4*)&c8[4] = *(const float4*)&ctxs[m * 64 + dg * 8 + 4];
        const float q0 = qp[(rg * 2) * 256 + m];
        const float q1 = qp[(rg * 2 + 1) * 256 + m];
#pragma unroll
        for (int j = 0; j < 8; ++j) {
            oacc[0][j] = fmaf(q0, c8[j], oacc[0][j]);
            oacc[1][j] = fmaf(q1, c8[j], oacc[1][j]);
        }
    }

    const float d0 = dinv[rg * 2];
    const float d1 = dinv[rg * 2 + 1];
#pragma unroll
    for (int i = 0; i < 2; ++i) {
        const float di = (i == 0) ? d0 : d1;
        float4 o0, o1;
        o0.x = oacc[i][0] * di; o0.y = oacc[i][1] * di;
        o0.z = oacc[i][2] * di; o0.w = oacc[i][3] * di;
        o1.x = oacc[i][4] * di; o1.y = oacc[i][5] * di;
        o1.z = oacc[i][6] * di; o1.w = oacc[i][7] * di;
        float* op = out + (size_t)(b * SEQ + n0 + rg * 2 + i) * HIDDEN + h * HD + dg * 8;
        *(float4*)op       = o0;
        *(float4*)(op + 4) = o1;
    }
}

// ============================================================
// launch
// ============================================================
extern "C" void kernel_launch(void* const* d_in, const int* in_sizes, int n_in,
                              void* d_out, int out_size)
{
    const float* x    = (const float*)d_in[0];
    const float* w    = (const float*)d_in[1];
    const float* bias = (const float*)d_in[2];
    const float* proj = (const float*)d_in[3];
    float* out = (float*)d_out;

    cudaFuncSetAttribute(ctx_kernel, cudaFuncAttributeMaxDynamicSharedMemorySize,
                         SMEM_B_FLOATS * (int)sizeof(float));
    cudaFuncSetAttribute(out_kernel, cudaFuncAttributeMaxDynamicSharedMemorySize,
                         SMEM_C_FLOATS * (int)sizeof(float));

    // Phase A: QKV GEMM
    qkv_gemm<<<dim3(QKVW / 128, NTOK / 128), 256>>>(x, w, bias);

    // Phase B: zero accumulators, then features + context/ksum
    zero_acc<<<(NBH * RP * HD + 255) / 256, 256>>>();
    ctx_kernel<<<dim3(8, NBH), 256, SMEM_B_FLOATS * sizeof(float)>>>(proj);

    // Phase C: q features + normalization + output
    out_kernel<<<dim3(SEQ / 64, NBH), 256, SMEM_C_FLOATS * sizeof(float)>>>(proj, out);
}

// round 9
// speedup vs baseline: 1.2965x; 1.2965x over previous
#include <cuda_runtime.h>
#include <cuda_bf16.h>
#include <cuda_pipeline.h>
#include <mma.h>
#include <cstdint>

using namespace nvcuda;

#define HIDDEN 1024
#define NHEADS 16
#define HD 64
#define RP 256
#define BATCH 4
#define SEQ 4096
#define NTOK (BATCH * SEQ)      /* 16384 */
#define QKVW (3 * HIDDEN)       /* 3072  */
#define NBH (BATCH * NHEADS)    /* 64    */
#define SCALE 0.125f
#define KEPS 1e-3f

// ---------------- scratch ----------------
__device__ float g_qkv[(size_t)NTOK * QKVW];               // 192 MB
__device__ float g_ctx[(size_t)NBH * RP * HD];             // 4 MB
__device__ float g_ksum[(size_t)NBH * RP];                 // 64 KB
__device__ __nv_bfloat16 g_xhi[(size_t)NTOK * HIDDEN];     // 32 MB
__device__ __nv_bfloat16 g_xlo[(size_t)NTOK * HIDDEN];     // 32 MB
__device__ __nv_bfloat16 g_wthi[(size_t)QKVW * HIDDEN];    // 6 MB  (W^T)
__device__ __nv_bfloat16 g_wtlo[(size_t)QKVW * HIDDEN];    // 6 MB

// ============================================================
// conv_x: fp32 -> bf16 hi/lo split
// ============================================================
__global__ void conv_x(const float* __restrict__ x)
{
    size_t i = (size_t)blockIdx.x * blockDim.x + threadIdx.x;   // 4 floats each
    if (i * 4 >= (size_t)NTOK * HIDDEN) return;
    float4 v = ((const float4*)x)[i];
    float h0 = __bfloat162float(__float2bfloat16(v.x));
    float h1 = __bfloat162float(__float2bfloat16(v.y));
    float h2 = __bfloat162float(__float2bfloat16(v.z));
    float h3 = __bfloat162float(__float2bfloat16(v.w));
    __nv_bfloat162* hp = (__nv_bfloat162*)g_xhi;
    __nv_bfloat162* lp = (__nv_bfloat162*)g_xlo;
    hp[i * 2]     = __nv_bfloat162(__float2bfloat16(h0), __float2bfloat16(h1));
    hp[i * 2 + 1] = __nv_bfloat162(__float2bfloat16(h2), __float2bfloat16(h3));
    lp[i * 2]     = __nv_bfloat162(__float2bfloat16(v.x - h0), __float2bfloat16(v.y - h1));
    lp[i * 2 + 1] = __nv_bfloat162(__float2bfloat16(v.z - h2), __float2bfloat16(v.w - h3));
}

// ============================================================
// conv_w: transpose + hi/lo split.  WT[n][k] = W[k][n]
// ============================================================
__global__ void conv_w(const float* __restrict__ w)
{
    __shared__ float tile[32][33];
    const int n0 = blockIdx.x * 32, k0 = blockIdx.y * 32;
    const int tx = threadIdx.x, ty = threadIdx.y;
    tile[ty][tx] = w[(size_t)(k0 + ty) * QKVW + n0 + tx];
    __syncthreads();
    const float v = tile[tx][ty];            // = W[k0+tx][n0+ty]
    const float h = __bfloat162float(__float2bfloat16(v));
    const size_t o = (size_t)(n0 + ty) * HIDDEN + k0 + tx;
    g_wthi[o] = __float2bfloat16(h);
    g_wtlo[o] = __float2bfloat16(v - h);
}

// ============================================================
// qkv_gemm_wmma: C[16384,3072] = X @ W + bias, wmma bf16 3-pass
// 128x128x32 CTA tile, 8 warps (4M x 2N), warp tile 32x64.
// __pipeline_memcpy_async double-buffered smem, rows padded to 40 halves.
// ============================================================
#define ROWP 40                              /* halves per smem row  */
#define TILEH (128 * ROWP)                   /* halves per tile      */
#define STAGEH (4 * TILEH)                   /* Ahi Alo Bhi Blo      */
#define SMEM_G (2 * STAGEH * 2)              /* 81920 bytes          */

__global__ __launch_bounds__(256, 1) void qkv_gemm_wmma(const float* __restrict__ bias)
{
    extern __shared__ __nv_bfloat16 smg[];
    __nv_bfloat16* sAh = smg;
    __nv_bfloat16* sAl = smg + TILEH;
    __nv_bfloat16* sBh = smg + 2 * TILEH;
    __nv_bfloat16* sBl = smg + 3 * TILEH;

    const int tid  = threadIdx.x;
    const int wid  = tid >> 5;
    const int col0 = blockIdx.x * 128, row0 = blockIdx.y * 128;
    const int warpM = wid >> 1;              // 0..3 -> 32 rows each
    const int warpN = wid & 1;               // 0..1 -> 64 cols each

    // loader mapping: 2 threads per row; each thread 2 x 16B segs per tile
    const int lrow = tid >> 1;               // 0..127
    const int lseg = (tid & 1) * 2;          // seg 0/1 or 2/3 (8 halves each)
    const __nv_bfloat16* gAh = g_xhi  + (size_t)(row0 + lrow) * HIDDEN + lseg * 8;
    const __nv_bfloat16* gAl = g_xlo  + (size_t)(row0 + lrow) * HIDDEN + lseg * 8;
    const __nv_bfloat16* gBh = g_wthi + (size_t)(col0 + lrow) * HIDDEN + lseg * 8;
    const __nv_bfloat16* gBl = g_wtlo + (size_t)(col0 + lrow) * HIDDEN + lseg * 8;
    const uint32_t soff = lrow * ROWP + lseg * 8;

    wmma::fragment<wmma::accumulator, 16, 16, 16, float> acc[2][4];
#pragma unroll
    for (int i = 0; i < 2; ++i)
#pragma unroll
        for (int j = 0; j < 4; ++j) wmma::fill_fragment(acc[i][j], 0.f);

    // prefetch stage 0
#pragma unroll
    for (int s = 0; s < 2; ++s) {
        __pipeline_memcpy_async(sAh + soff + s * 8, gAh + s * 8, 16);
        __pipeline_memcpy_async(sAl + soff + s * 8, gAl + s * 8, 16);
        __pipeline_memcpy_async(sBh + soff + s * 8, gBh + s * 8, 16);
        __pipeline_memcpy_async(sBl + soff + s * 8, gBl + s * 8, 16);
    }
    __pipeline_commit();

    int buf = 0;
    for (int kt = 0; kt < 32; ++kt) {
        if (kt < 31) {
            const uint32_t d = (buf ^ 1) * STAGEH + soff;
            const size_t gofs = (size_t)(kt + 1) * 32;
#pragma unroll
            for (int s = 0; s < 2; ++s) {
                __pipeline_memcpy_async(sAh + d + s * 8, gAh + gofs + s * 8, 16);
                __pipeline_memcpy_async(sAl + d + s * 8, gAl + gofs + s * 8, 16);
                __pipeline_memcpy_async(sBh + d + s * 8, gBh + gofs + s * 8, 16);
                __pipeline_memcpy_async(sBl + d + s * 8, gBl + gofs + s * 8, 16);
            }
            __pipeline_commit();
            __pipeline_wait_prior(1);
        } else {
            __pipeline_wait_prior(0);
        }
        __syncthreads();

        const uint32_t sb = buf * STAGEH;
#pragma unroll
        for (int ks = 0; ks < 2; ++ks) {
            wmma::fragment<wmma::matrix_a, 16, 16, 16, __nv_bfloat16, wmma::row_major> ah[2], al[2];
            wmma::fragment<wmma::matrix_b, 16, 16, 16, __nv_bfloat16, wmma::col_major> bh[4], bl[4];
#pragma unroll
            for (int mt = 0; mt < 2; ++mt) {
                const uint32_t ao = sb + (warpM * 32 + mt * 16) * ROWP + ks * 16;
                wmma::load_matrix_sync(ah[mt], sAh + ao, ROWP);
                wmma::load_matrix_sync(al[mt], sAl + ao, ROWP);
            }
#pragma unroll
            for (int nt = 0; nt < 4; ++nt) {
                const uint32_t bo = sb + (warpN * 64 + nt * 16) * ROWP + ks * 16;
                wmma::load_matrix_sync(bh[nt], sBh + bo, ROWP);
                wmma::load_matrix_sync(bl[nt], sBl + bo, ROWP);
            }
#pragma unroll
            for (int mt = 0; mt < 2; ++mt)
#pragma unroll
                for (int nt = 0; nt < 4; ++nt) {
                    wmma::mma_sync(acc[mt][nt], ah[mt], bh[nt], acc[mt][nt]);
                    wmma::mma_sync(acc[mt][nt], ah[mt], bl[nt], acc[mt][nt]);
                    wmma::mma_sync(acc[mt][nt], al[mt], bh[nt], acc[mt][nt]);
                }
        }
        __syncthreads();
        buf ^= 1;
    }

    // epilogue: park C in smem (64 KB <= 80 KB), then bias-add + store
    float* Cs = (float*)smg;
#pragma unroll
    for (int mt = 0; mt < 2; ++mt)
#pragma unroll
        for (int nt = 0; nt < 4; ++nt)
            wmma::store_matrix_sync(Cs + (warpM * 32 + mt * 16) * 128 + warpN * 64 + nt * 16,
                                    acc[mt][nt], 128, wmma::mem_row_major);
    __syncthreads();

#pragma unroll
    for (int i = 0; i < 16; ++i) {
        const int u = i * 256 + tid;         // 4096 float4 units
        const int row = u >> 5, c4 = (u & 31) * 4;
        float4 v = *(float4*)&Cs[row * 128 + c4];
        const float4 bv = *(const float4*)&bias[col0 + c4];
        v.x += bv.x; v.y += bv.y; v.z += bv.z; v.w += bv.w;
        *(float4*)(g_qkv + (size_t)(row0 + row) * QKVW + col0 + c4) = v;
    }
}

// ============================================================
// Zero kernel: clears context + ksum accumulators
// ============================================================
__global__ void zero_acc()
{
    const int i = blockIdx.x * blockDim.x + threadIdx.x;
    if (i < NBH * RP * HD) g_ctx[i] = 0.f;
    if (i < NBH * RP)      g_ksum[i] = 0.f;
}

// ============================================================
// Kernel B: per (chunk, bh): k' features + context/ksum accumulation
// ============================================================
#define SMEM_B_FLOATS (64 * 256 + 64 * 64 + 64 * 64 + 64 * 256)

__global__ __launch_bounds__(256) void ctx_kernel(const float* __restrict__ proj)
{
    extern __shared__ float sm[];
    float* projT = sm;                    // [kk][m]
    float* kbuf  = projT + 64 * 256;      // [r][kk]
    float* vbuf  = kbuf + 64 * 64;        // [r][d]
    float* kp    = vbuf + 64 * 64;        // [r][m]

    const int tid   = threadIdx.x;
    const int lane  = tid & 31;
    const int w     = tid >> 5;
    const int chunk = blockIdx.x;
    const int bh    = blockIdx.y;
    const int b     = bh >> 4, h = bh & 15;

    for (int idx = tid; idx < 64 * 256; idx += 256) {
        const int m = idx & 255, kk = idx >> 8;
        projT[kk * 256 + m] = proj[m * 64 + kk];
    }

    const int mg = tid >> 3;
    const int dg = tid & 7;
    float cacc[8][8];
#pragma unroll
    for (int i = 0; i < 8; ++i)
#pragma unroll
        for (int j = 0; j < 8; ++j) cacc[i][j] = 0.f;
    float ks_acc[8];
#pragma unroll
    for (int i = 0; i < 8; ++i) ks_acc[i] = 0.f;

    const float* qkvb = g_qkv + (size_t)b * SEQ * QKVW;
    const int kcol = HIDDEN + h * HD;
    const int vcol = 2 * HIDDEN + h * HD;
    const int r_ld = tid >> 2;
    const int c_ld = (tid & 3) << 4;

    __syncthreads();

    for (int st = 0; st < 8; ++st) {
        const int n0 = chunk * 512 + st * 64;
#pragma unroll
        for (int q = 0; q < 4; ++q) {
            const size_t rbase = (size_t)(n0 + r_ld) * QKVW;
            float4 kv = *(const float4*)(qkvb + rbase + kcol + c_ld + q * 4);
            kv.x *= SCALE; kv.y *= SCALE; kv.z *= SCALE; kv.w *= SCALE;
            *(float4*)&kbuf[r_ld * 64 + c_ld + q * 4] = kv;
            *(float4*)&vbuf[r_ld * 64 + c_ld + q * 4] =
                *(const float4*)(qkvb + rbase + vcol + c_ld + q * 4);
        }
        __syncthreads();

        {
            float facc[8][8];
#pragma unroll
            for (int i = 0; i < 8; ++i)
#pragma unroll
                for (int j = 0; j < 8; ++j) facc[i][j] = 0.f;
#pragma unroll 4
            for (int kk = 0; kk < 64; ++kk) {
                float pj[8];
#pragma unroll
                for (int j = 0; j < 8; ++j) pj[j] = projT[kk * 256 + lane + 32 * j];
#pragma unroll
                for (int i = 0; i < 8; ++i) {
                    const float kv = kbuf[(w * 8 + i) * 64 + kk];
#pragma unroll
                    for (int j = 0; j < 8; ++j)
                        facc[i][j] = fmaf(kv, pj[j], facc[i][j]);
                }
            }
#pragma unroll
            for (int i = 0; i < 8; ++i)
#pragma unroll
                for (int j = 0; j < 8; ++j)
                    kp[(w * 8 + i) * 256 + lane + 32 * j] =
                        fmaxf(facc[i][j], 0.f) + KEPS;
        }
        __syncthreads();

#pragma unroll 4
        for (int r = 0; r < 64; ++r) {
            float kpv[8], vv[8];
            *(float4*)&kpv[0] = *(const float4*)&kp[r * 256 + mg * 8];
            *(float4*)&kpv[4] = *(const float4*)&kp[r * 256 + mg * 8 + 4];
            *(float4*)&vv[0]  = *(const float4*)&vbuf[r * 64 + dg * 8];
            *(float4*)&vv[4]  = *(const float4*)&vbuf[r * 64 + dg * 8 + 4];
#pragma unroll
            for (int i = 0; i < 8; ++i)
#pragma unroll
                for (int j = 0; j < 8; ++j)
                    cacc[i][j] = fmaf(kpv[i], vv[j], cacc[i][j]);
            if (dg == 0) {
#pragma unroll
                for (int i = 0; i < 8; ++i) ks_acc[i] += kpv[i];
            }
        }
        __syncthreads();
    }

    float* ctx_out = g_ctx + (size_t)bh * RP * HD;
#pragma unroll
    for (int i = 0; i < 8; ++i)
#pragma unroll
        for (int j = 0; j < 8; ++j)
            atomicAdd(&ctx_out[(mg * 8 + i) * HD + dg * 8 + j], cacc[i][j]);
    if (dg == 0) {
#pragma unroll
        for (int i = 0; i < 8; ++i)
            atomicAdd(&g_ksum[bh * RP + mg * 8 + i], ks_acc[i]);
    }
}

// ============================================================
// Kernel C: q' features + denom + out = (q' @ ctx) * dinv
// ============================================================
#define SMEM_C_FLOATS (64 * 256 + 256 * 64 + 64 * 256 + 64 * 64 + 256 + 64)

__global__ __launch_bounds__(256) void out_kernel(const float* __restrict__ proj,
                                                  float* __restrict__ out)
{
    extern __shared__ float sm[];
    float* projT = sm;
    float* ctxs  = projT + 64 * 256;
    float* qp    = ctxs + 256 * 64;
    float* qbuf  = qp + 64 * 256;
    float* ksums = qbuf + 64 * 64;
    float* dinv  = ksums + 256;

    const int tid  = threadIdx.x;
    const int lane = tid & 31;
    const int w    = tid >> 5;
    const int tile = blockIdx.x;
    const int bh   = blockIdx.y;
    const int b    = bh >> 4, h = bh & 15;
    const int n0   = tile * 64;

    for (int idx = tid; idx < 64 * 256; idx += 256) {
        const int m = idx & 255, kk = idx >> 8;
        projT[kk * 256 + m] = proj[m * 64 + kk];
    }
    for (int idx = tid; idx < 256 * 64; idx += 256)
        ctxs[idx] = g_ctx[(size_t)bh * RP * HD + idx];
    if (tid < 256) ksums[tid] = g_ksum[bh * RP + tid];

    {
        const float* qkvb = g_qkv + (size_t)b * SEQ * QKVW;
        const int qcol = h * HD;
        const int r_ld = tid >> 2;
        const int c_ld = (tid & 3) << 4;
#pragma unroll
        for (int q = 0; q < 4; ++q) {
            float4 qv = *(const float4*)(qkvb + (size_t)(n0 + r_ld) * QKVW + qcol + c_ld + q * 4);
            qv.x *= SCALE; qv.y *= SCALE; qv.z *= SCALE; qv.w *= SCALE;
            *(float4*)&qbuf[r_ld * 64 + c_ld + q * 4] = qv;
        }
    }
    __syncthreads();

    {
        float facc[8][8];
#pragma unroll
        for (int i = 0; i < 8; ++i)
#pragma unroll
            for (int j = 0; j < 8; ++j) facc[i][j] = 0.f;
#pragma unroll 4
        for (int kk = 0; kk < 64; ++kk) {
            float pj[8];
#pragma unroll
            for (int j = 0; j < 8; ++j) pj[j] = projT[kk * 256 + lane + 32 * j];
#pragma unroll
            for (int i = 0; i < 8; ++i) {
                const float qv = qbuf[(w * 8 + i) * 64 + kk];
#pragma unroll
                for (int j = 0; j < 8; ++j)
                    facc[i][j] = fmaf(qv, pj[j], facc[i][j]);
            }
        }
#pragma unroll
        for (int i = 0; i < 8; ++i) {
            float dsum = 0.f;
#pragma unroll
            for (int j = 0; j < 8; ++j) {
                const float v = fmaxf(facc[i][j], 0.f) + KEPS;
                qp[(w * 8 + i) * 256 + lane + 32 * j] = v;
                dsum = fmaf(v, ksums[lane + 32 * j], dsum);
            }
#pragma unroll
            for (int off = 16; off > 0; off >>= 1)
                dsum += __shfl_xor_sync(0xFFFFFFFFu, dsum, off);
            if (lane == 0) dinv[w * 8 + i] = 1.0f / dsum;
        }
    }
    __syncthreads();

    const int rg = tid >> 3;
    const int dg = tid & 7;
    float oacc[2][8];
#pragma unroll
    for (int i = 0; i < 2; ++i)
#pragma unroll
        for (int j = 0; j < 8; ++j) oacc[i][j] = 0.f;

#pragma unroll 4
    for (int m = 0; m < 256; ++m) {
        float c8[8];
        *(float4*)&c8[0] = *(const float4*)&ctxs[m * 64 + dg * 8];
        *(float4*)&c8[4] = *(const float4*)&ctxs[m * 64 + dg * 8 + 4];
        const float q0 = qp[(rg * 2) * 256 + m];
        const float q1 = qp[(rg * 2 + 1) * 256 + m];
#pragma unroll
        for (int j = 0; j < 8; ++j) {
            oacc[0][j] = fmaf(q0, c8[j], oacc[0][j]);
            oacc[1][j] = fmaf(q1, c8[j], oacc[1][j]);
        }
    }

    const float d0 = dinv[rg * 2];
    const float d1 = dinv[rg * 2 + 1];
#pragma unroll
    for (int i = 0; i < 2; ++i) {
        const float di = (i == 0) ? d0 : d1;
        float4 o0, o1;
        o0.x = oacc[i][0] * di; o0.y = oacc[i][1] * di;
        o0.z = oacc[i][2] * di; o0.w = oacc[i][3] * di;
        o1.x = oacc[i][4] * di; o1.y = oacc[i][5] * di;
        o1.z = oacc[i][6] * di; o1.w = oacc[i][7] * di;
        float* op = out + (size_t)(b * SEQ + n0 + rg * 2 + i) * HIDDEN + h * HD + dg * 8;
        *(float4*)op       = o0;
        *(float4*)(op + 4) = o1;
    }
}

// ============================================================
// launch
// ============================================================
extern "C" void kernel_launch(void* const* d_in, const int* in_sizes, int n_in,
                              void* d_out, int out_size)
{
    const float* x    = (const float*)d_in[0];
    const float* w    = (const float*)d_in[1];
    const float* bias = (const float*)d_in[2];
    const float* proj = (const float*)d_in[3];
    float* out = (float*)d_out;

    cudaFuncSetAttribute(qkv_gemm_wmma, cudaFuncAttributeMaxDynamicSharedMemorySize, SMEM_G);
    cudaFuncSetAttribute(ctx_kernel, cudaFuncAttributeMaxDynamicSharedMemorySize,
                         SMEM_B_FLOATS * (int)sizeof(float));
    cudaFuncSetAttribute(out_kernel, cudaFuncAttributeMaxDynamicSharedMemorySize,
                         SMEM_C_FLOATS * (int)sizeof(float));

    // Phase A: split-precision conversion + tensor-core QKV GEMM (wmma)
    conv_x<<<NTOK * HIDDEN / 4 / 256, 256>>>(x);
    conv_w<<<dim3(QKVW / 32, HIDDEN / 32), dim3(32, 32)>>>(w);
    qkv_gemm_wmma<<<dim3(QKVW / 128, NTOK / 128), 256, SMEM_G>>>(bias);

    // Phase B: zero accumulators, then features + context/ksum
    zero_acc<<<(NBH * RP * HD + 255) / 256, 256>>>();
    ctx_kernel<<<dim3(8, NBH), 256, SMEM_B_FLOATS * sizeof(float)>>>(proj);

    // Phase C: q features + normalization + output
    out_kernel<<<dim3(SEQ / 64, NBH), 256, SMEM_C_FLOATS * sizeof(float)>>>(proj, out);
}

// round 12
// speedup vs baseline: 1.3123x; 1.0122x over previous
#include <cuda_runtime.h>
#include <cuda_bf16.h>
#include <cuda_pipeline.h>
#include <mma.h>
#include <cstdint>

using namespace nvcuda;

#define HIDDEN 1024
#define NHEADS 16
#define HD 64
#define RP 256
#define BATCH 4
#define SEQ 4096
#define NTOK (BATCH * SEQ)      /* 16384 */
#define QKVW (3 * HIDDEN)       /* 3072  */
#define NBH (BATCH * NHEADS)    /* 64    */
#define SCALE 0.125f
#define KEPS 1e-3f

// ---------------- scratch ----------------
__device__ float g_qkv[(size_t)NTOK * QKVW];               // 192 MB
__device__ float g_ctx[(size_t)NBH * RP * HD];             // 4 MB
__device__ float g_ksum[(size_t)NBH * RP];                 // 64 KB
__device__ __nv_bfloat16 g_xhi[(size_t)NTOK * HIDDEN];     // 32 MB
__device__ __nv_bfloat16 g_xlo[(size_t)NTOK * HIDDEN];     // 32 MB
__device__ __nv_bfloat16 g_wthi[(size_t)QKVW * HIDDEN];    // 6 MB (W^T)
__device__ __nv_bfloat16 g_wtlo[(size_t)QKVW * HIDDEN];    // 6 MB

__device__ __forceinline__ void split2(float v, __nv_bfloat16& hi, __nv_bfloat16& lo) {
    hi = __float2bfloat16(v);
    lo = __float2bfloat16(v - __bfloat162float(hi));
}

// ============================================================
// conv_x: fp32 -> bf16 hi/lo split
// ============================================================
__global__ void conv_x(const float* __restrict__ x)
{
    size_t i = (size_t)blockIdx.x * blockDim.x + threadIdx.x;
    if (i * 4 >= (size_t)NTOK * HIDDEN) return;
    float4 v = ((const float4*)x)[i];
    __nv_bfloat16 h[4], l[4];
    split2(v.x, h[0], l[0]); split2(v.y, h[1], l[1]);
    split2(v.z, h[2], l[2]); split2(v.w, h[3], l[3]);
    __nv_bfloat162* hp = (__nv_bfloat162*)g_xhi;
    __nv_bfloat162* lp = (__nv_bfloat162*)g_xlo;
    hp[i * 2]     = __nv_bfloat162(h[0], h[1]);
    hp[i * 2 + 1] = __nv_bfloat162(h[2], h[3]);
    lp[i * 2]     = __nv_bfloat162(l[0], l[1]);
    lp[i * 2 + 1] = __nv_bfloat162(l[2], l[3]);
}

// ============================================================
// conv_w: transpose + hi/lo split.  WT[n][k] = W[k][n]
// ============================================================
__global__ void conv_w(const float* __restrict__ w)
{
    __shared__ float tile[32][33];
    const int n0 = blockIdx.x * 32, k0 = blockIdx.y * 32;
    const int tx = threadIdx.x, ty = threadIdx.y;
    tile[ty][tx] = w[(size_t)(k0 + ty) * QKVW + n0 + tx];
    __syncthreads();
    const float v = tile[tx][ty];
    __nv_bfloat16 hi, lo; split2(v, hi, lo);
    const size_t o = (size_t)(n0 + ty) * HIDDEN + k0 + tx;
    g_wthi[o] = hi; g_wtlo[o] = lo;
}

// ============================================================
// qkv_gemm_wmma2: 512 thr, 16 warps (4Mx4N), warp tile 32x32, BK=32
// 3-pass bf16 hi/lo; fp32 epilogue (proven R9 format).
// ============================================================
#define ROWP 40
#define TILEH (128 * ROWP)
#define STAGEH (4 * TILEH)
#define SMEM_G (2 * STAGEH * 2)              /* 81920 B */

__global__ __launch_bounds__(512, 1) void qkv_gemm_wmma2(const float* __restrict__ bias)
{
    extern __shared__ __nv_bfloat16 smg[];
    __nv_bfloat16* sAh = smg;
    __nv_bfloat16* sAl = smg + TILEH;
    __nv_bfloat16* sBh = smg + 2 * TILEH;
    __nv_bfloat16* sBl = smg + 3 * TILEH;

    const int tid  = threadIdx.x;
    const int wid  = tid >> 5;
    const int col0 = blockIdx.x * 128, row0 = blockIdx.y * 128;
    const int warpM = wid >> 2;              // 0..3 -> 32 rows
    const int warpN = wid & 3;               // 0..3 -> 32 cols

    const int lrow = tid >> 2;               // 0..127
    const int lseg = tid & 3;                // 16B seg
    const __nv_bfloat16* gAh = g_xhi  + (size_t)(row0 + lrow) * HIDDEN + lseg * 8;
    const __nv_bfloat16* gAl = g_xlo  + (size_t)(row0 + lrow) * HIDDEN + lseg * 8;
    const __nv_bfloat16* gBh = g_wthi + (size_t)(col0 + lrow) * HIDDEN + lseg * 8;
    const __nv_bfloat16* gBl = g_wtlo + (size_t)(col0 + lrow) * HIDDEN + lseg * 8;
    const uint32_t soff = lrow * ROWP + lseg * 8;

    wmma::fragment<wmma::accumulator, 16, 16, 16, float> acc[2][2];
#pragma unroll
    for (int i = 0; i < 2; ++i)
#pragma unroll
        for (int j = 0; j < 2; ++j) wmma::fill_fragment(acc[i][j], 0.f);

    __pipeline_memcpy_async(sAh + soff, gAh, 16);
    __pipeline_memcpy_async(sAl + soff, gAl, 16);
    __pipeline_memcpy_async(sBh + soff, gBh, 16);
    __pipeline_memcpy_async(sBl + soff, gBl, 16);
    __pipeline_commit();

    int buf = 0;
    for (int kt = 0; kt < 32; ++kt) {
        if (kt < 31) {
            const uint32_t d = (buf ^ 1) * STAGEH + soff;
            const size_t g = (size_t)(kt + 1) * 32;
            __pipeline_memcpy_async(sAh + d, gAh + g, 16);
            __pipeline_memcpy_async(sAl + d, gAl + g, 16);
            __pipeline_memcpy_async(sBh + d, gBh + g, 16);
            __pipeline_memcpy_async(sBl + d, gBl + g, 16);
            __pipeline_commit();
            __pipeline_wait_prior(1);
        } else {
            __pipeline_wait_prior(0);
        }
        __syncthreads();

        const uint32_t sb = buf * STAGEH;
#pragma unroll
        for (int ks = 0; ks < 2; ++ks) {
            wmma::fragment<wmma::matrix_a, 16, 16, 16, __nv_bfloat16, wmma::row_major> ah[2], al[2];
            wmma::fragment<wmma::matrix_b, 16, 16, 16, __nv_bfloat16, wmma::col_major> bh[2], bl[2];
#pragma unroll
            for (int mt = 0; mt < 2; ++mt) {
                const uint32_t ao = sb + (warpM * 32 + mt * 16) * ROWP + ks * 16;
                wmma::load_matrix_sync(ah[mt], sAh + ao, ROWP);
                wmma::load_matrix_sync(al[mt], sAl + ao, ROWP);
            }
#pragma unroll
            for (int nt = 0; nt < 2; ++nt) {
                const uint32_t bo = sb + (warpN * 32 + nt * 16) * ROWP + ks * 16;
                wmma::load_matrix_sync(bh[nt], sBh + bo, ROWP);
                wmma::load_matrix_sync(bl[nt], sBl + bo, ROWP);
            }
#pragma unroll
            for (int mt = 0; mt < 2; ++mt)
#pragma unroll
                for (int nt = 0; nt < 2; ++nt) {
                    wmma::mma_sync(acc[mt][nt], ah[mt], bh[nt], acc[mt][nt]);
                    wmma::mma_sync(acc[mt][nt], ah[mt], bl[nt], acc[mt][nt]);
                    wmma::mma_sync(acc[mt][nt], al[mt], bh[nt], acc[mt][nt]);
                }
        }
        __syncthreads();
        buf ^= 1;
    }

    // park C in smem, then bias-add + fp32 store (proven R9 epilogue)
    float* Cs = (float*)smg;
#pragma unroll
    for (int mt = 0; mt < 2; ++mt)
#pragma unroll
        for (int nt = 0; nt < 2; ++nt)
            wmma::store_matrix_sync(Cs + (warpM * 32 + mt * 16) * 128 + warpN * 32 + nt * 16,
                                    acc[mt][nt], 128, wmma::mem_row_major);
    __syncthreads();

#pragma unroll
    for (int i = 0; i < 8; ++i) {
        const int u = i * 512 + tid;         // 4096 float4 units
        const int row = u >> 5, c4 = (u & 31) * 4;
        float4 v = *(float4*)&Cs[row * 128 + c4];
        const float4 bv = *(const float4*)&bias[col0 + c4];
        v.x += bv.x; v.y += bv.y; v.z += bv.z; v.w += bv.w;
        *(float4*)(g_qkv + (size_t)(row0 + row) * QKVW + col0 + c4) = v;
    }
}

// ============================================================
// zero_acc
// ============================================================
__global__ void zero_acc()
{
    const int i = blockIdx.x * blockDim.x + threadIdx.x;
    if (i < NBH * RP * HD) g_ctx[i] = 0.f;
    if (i < NBH * RP)      g_ksum[i] = 0.f;
}

// ============================================================
// Kernel B (proven R9 scalar): k' features + context/ksum
// ============================================================
#define SMEM_B_FLOATS (64 * 256 + 64 * 64 + 64 * 64 + 64 * 256)

__global__ __launch_bounds__(256) void ctx_kernel(const float* __restrict__ proj)
{
    extern __shared__ float sm[];
    float* projT = sm;                    // [kk][m]
    float* kbuf  = projT + 64 * 256;      // [r][kk]
    float* vbuf  = kbuf + 64 * 64;        // [r][d]
    float* kp    = vbuf + 64 * 64;        // [r][m]

    const int tid   = threadIdx.x;
    const int lane  = tid & 31;
    const int w     = tid >> 5;
    const int chunk = blockIdx.x;
    const int bh    = blockIdx.y;
    const int b     = bh >> 4, h = bh & 15;

    for (int idx = tid; idx < 64 * 256; idx += 256) {
        const int m = idx & 255, kk = idx >> 8;
        projT[kk * 256 + m] = proj[m * 64 + kk];
    }

    const int mg = tid >> 3;
    const int dg = tid & 7;
    float cacc[8][8];
#pragma unroll
    for (int i = 0; i < 8; ++i)
#pragma unroll
        for (int j = 0; j < 8; ++j) cacc[i][j] = 0.f;
    float ks_acc[8];
#pragma unroll
    for (int i = 0; i < 8; ++i) ks_acc[i] = 0.f;

    const float* qkvb = g_qkv + (size_t)b * SEQ * QKVW;
    const int kcol = HIDDEN + h * HD;
    const int vcol = 2 * HIDDEN + h * HD;
    const int r_ld = tid >> 2;
    const int c_ld = (tid & 3) << 4;

    __syncthreads();

    for (int st = 0; st < 8; ++st) {
        const int n0 = chunk * 512 + st * 64;
#pragma unroll
        for (int q = 0; q < 4; ++q) {
            const size_t rbase = (size_t)(n0 + r_ld) * QKVW;
            float4 kv = *(const float4*)(qkvb + rbase + kcol + c_ld + q * 4);
            kv.x *= SCALE; kv.y *= SCALE; kv.z *= SCALE; kv.w *= SCALE;
            *(float4*)&kbuf[r_ld * 64 + c_ld + q * 4] = kv;
            *(float4*)&vbuf[r_ld * 64 + c_ld + q * 4] =
                *(const float4*)(qkvb + rbase + vcol + c_ld + q * 4);
        }
        __syncthreads();

        {
            float facc[8][8];
#pragma unroll
            for (int i = 0; i < 8; ++i)
#pragma unroll
                for (int j = 0; j < 8; ++j) facc[i][j] = 0.f;
#pragma unroll 4
            for (int kk = 0; kk < 64; ++kk) {
                float pj[8];
#pragma unroll
                for (int j = 0; j < 8; ++j) pj[j] = projT[kk * 256 + lane + 32 * j];
#pragma unroll
                for (int i = 0; i < 8; ++i) {
                    const float kv = kbuf[(w * 8 + i) * 64 + kk];
#pragma unroll
                    for (int j = 0; j < 8; ++j)
                        facc[i][j] = fmaf(kv, pj[j], facc[i][j]);
                }
            }
#pragma unroll
            for (int i = 0; i < 8; ++i)
#pragma unroll
                for (int j = 0; j < 8; ++j)
                    kp[(w * 8 + i) * 256 + lane + 32 * j] =
                        fmaxf(facc[i][j], 0.f) + KEPS;
        }
        __syncthreads();

#pragma unroll 4
        for (int r = 0; r < 64; ++r) {
            float kpv[8], vv[8];
            *(float4*)&kpv[0] = *(const float4*)&kp[r * 256 + mg * 8];
            *(float4*)&kpv[4] = *(const float4*)&kp[r * 256 + mg * 8 + 4];
            *(float4*)&vv[0]  = *(const float4*)&vbuf[r * 64 + dg * 8];
            *(float4*)&vv[4]  = *(const float4*)&vbuf[r * 64 + dg * 8 + 4];
#pragma unroll
            for (int i = 0; i < 8; ++i)
#pragma unroll
                for (int j = 0; j < 8; ++j)
                    cacc[i][j] = fmaf(kpv[i], vv[j], cacc[i][j]);
            if (dg == 0) {
#pragma unroll
                for (int i = 0; i < 8; ++i) ks_acc[i] += kpv[i];
            }
        }
        __syncthreads();
    }

    float* ctx_out = g_ctx + (size_t)bh * RP * HD;
#pragma unroll
    for (int i = 0; i < 8; ++i)
#pragma unroll
        for (int j = 0; j < 8; ++j)
            atomicAdd(&ctx_out[(mg * 8 + i) * HD + dg * 8 + j], cacc[i][j]);
    if (dg == 0) {
#pragma unroll
        for (int i = 0; i < 8; ++i)
            atomicAdd(&g_ksum[bh * RP + mg * 8 + i], ks_acc[i]);
    }
}

// ============================================================
// Kernel C (proven R9 scalar): q' features + denom + out
// ============================================================
#define SMEM_C_FLOATS (64 * 256 + 256 * 64 + 64 * 256 + 64 * 64 + 256 + 64)

__global__ __launch_bounds__(256) void out_kernel(const float* __restrict__ proj,
                                                  float* __restrict__ out)
{
    extern __shared__ float sm[];
    float* projT = sm;
    float* ctxs  = projT + 64 * 256;
    float* qp    = ctxs + 256 * 64;
    float* qbuf  = qp + 64 * 256;
    float* ksums = qbuf + 64 * 64;
    float* dinv  = ksums + 256;

    const int tid  = threadIdx.x;
    const int lane = tid & 31;
    const int w    = tid >> 5;
    const int tile = blockIdx.x;
    const int bh   = blockIdx.y;
    const int b    = bh >> 4, h = bh & 15;
    const int n0   = tile * 64;

    for (int idx = tid; idx < 64 * 256; idx += 256) {
        const int m = idx & 255, kk = idx >> 8;
        projT[kk * 256 + m] = proj[m * 64 + kk];
    }
    for (int idx = tid; idx < 256 * 64; idx += 256)
        ctxs[idx] = g_ctx[(size_t)bh * RP * HD + idx];
    if (tid < 256) ksums[tid] = g_ksum[bh * RP + tid];

    {
        const float* qkvb = g_qkv + (size_t)b * SEQ * QKVW;
        const int qcol = h * HD;
        const int r_ld = tid >> 2;
        const int c_ld = (tid & 3) << 4;
#pragma unroll
        for (int q = 0; q < 4; ++q) {
            float4 qv = *(const float4*)(qkvb + (size_t)(n0 + r_ld) * QKVW + qcol + c_ld + q * 4);
            qv.x *= SCALE; qv.y *= SCALE; qv.z *= SCALE; qv.w *= SCALE;
            *(float4*)&qbuf[r_ld * 64 + c_ld + q * 4] = qv;
        }
    }
    __syncthreads();

    {
        float facc[8][8];
#pragma unroll
        for (int i = 0; i < 8; ++i)
#pragma unroll
            for (int j = 0; j < 8; ++j) facc[i][j] = 0.f;
#pragma unroll 4
        for (int kk = 0; kk < 64; ++kk) {
            float pj[8];
#pragma unroll
            for (int j = 0; j < 8; ++j) pj[j] = projT[kk * 256 + lane + 32 * j];
#pragma unroll
            for (int i = 0; i < 8; ++i) {
                const float qv = qbuf[(w * 8 + i) * 64 + kk];
#pragma unroll
                for (int j = 0; j < 8; ++j)
                    facc[i][j] = fmaf(qv, pj[j], facc[i][j]);
            }
        }
#pragma unroll
        for (int i = 0; i < 8; ++i) {
            float dsum = 0.f;
#pragma unroll
            for (int j = 0; j < 8; ++j) {
                const float v = fmaxf(facc[i][j], 0.f) + KEPS;
                qp[(w * 8 + i) * 256 + lane + 32 * j] = v;
                dsum = fmaf(v, ksums[lane + 32 * j], dsum);
            }
#pragma unroll
            for (int off = 16; off > 0; off >>= 1)
                dsum += __shfl_xor_sync(0xFFFFFFFFu, dsum, off);
            if (lane == 0) dinv[w * 8 + i] = 1.0f / dsum;
        }
    }
    __syncthreads();

    const int rg = tid >> 3;
    const int dg = tid & 7;
    float oacc[2][8];
#pragma unroll
    for (int i = 0; i < 2; ++i)
#pragma unroll
        for (int j = 0; j < 8; ++j) oacc[i][j] = 0.f;

#pragma unroll 4
    for (int m = 0; m < 256; ++m) {
        float c8[8];
        *(float4*)&c8[0] = *(const float4*)&ctxs[m * 64 + dg * 8];
        *(float4*)&c8[4] = *(const float4*)&ctxs[m * 64 + dg * 8 + 4];
        const float q0 = qp[(rg * 2) * 256 + m];
        const float q1 = qp[(rg * 2 + 1) * 256 + m];
#pragma unroll
        for (int j = 0; j < 8; ++j) {
            oacc[0][j] = fmaf(q0, c8[j], oacc[0][j]);
            oacc[1][j] = fmaf(q1, c8[j], oacc[1][j]);
        }
    }

    const float d0 = dinv[rg * 2];
    const float d1 = dinv[rg * 2 + 1];
#pragma unroll
    for (int i = 0; i < 2; ++i) {
        const float di = (i == 0) ? d0 : d1;
        float4 o0, o1;
        o0.x = oacc[i][0] * di; o0.y = oacc[i][1] * di;
        o0.z = oacc[i][2] * di; o0.w = oacc[i][3] * di;
        o1.x = oacc[i][4] * di; o1.y = oacc[i][5] * di;
        o1.z = oacc[i][6] * di; o1.w = oacc[i][7] * di;
        float* op = out + (size_t)(b * SEQ + n0 + rg * 2 + i) * HIDDEN + h * HD + dg * 8;
        *(float4*)op       = o0;
        *(float4*)(op + 4) = o1;
    }
}

// ============================================================
// launch
// ============================================================
extern "C" void kernel_launch(void* const* d_in, const int* in_sizes, int n_in,
                              void* d_out, int out_size)
{
    const float* x    = (const float*)d_in[0];
    const float* w    = (const float*)d_in[1];
    const float* bias = (const float*)d_in[2];
    const float* proj = (const float*)d_in[3];
    float* out = (float*)d_out;

    cudaFuncSetAttribute(qkv_gemm_wmma2, cudaFuncAttributeMaxDynamicSharedMemorySize, SMEM_G);
    cudaFuncSetAttribute(ctx_kernel, cudaFuncAttributeMaxDynamicSharedMemorySize,
                         SMEM_B_FLOATS * (int)sizeof(float));
    cudaFuncSetAttribute(out_kernel, cudaFuncAttributeMaxDynamicSharedMemorySize,
                         SMEM_C_FLOATS * (int)sizeof(float));

    conv_x<<<NTOK * HIDDEN / 4 / 256, 256>>>(x);
    conv_w<<<dim3(QKVW / 32, HIDDEN / 32), dim3(32, 32)>>>(w);

    qkv_gemm_wmma2<<<dim3(QKVW / 128, NTOK / 128), 512, SMEM_G>>>(bias);

    zero_acc<<<(NBH * RP * HD + 255) / 256, 256>>>();
    ctx_kernel<<<dim3(8, NBH), 256, SMEM_B_FLOATS * sizeof(float)>>>(proj);

    out_kernel<<<dim3(SEQ / 64, NBH), 256, SMEM_C_FLOATS * sizeof(float)>>>(proj, out);
}